// round 15
// baseline (speedup 1.0000x reference)
#include <cuda_runtime.h>
#include <cuda_bf16.h>
#include <cuda_fp16.h>
#include <stdint.h>
#include <cstdint>
#include <math.h>

#define DM   1024      // d_model
#define VOC  50264
#define DS   16        // d_state
#define DI   2048      // d_inner
#define DTR  64        // dt_rank
#define LSEQ 2048
#define XDBL 96        // dt_rank + 2*d_state
#define KSPL 16        // split-K factor for x_proj
#define PSTRIDE (LSEQ * XDBL)
#define SCH  8         // scan chunks
#define CL   (LSEQ / SCH)
#define NDN  (DI * DS) // 32768

// ---------------- scratch (device globals; no allocation allowed) ----------------
__device__ float g_x[LSEQ * DM];        // residual stream
__device__ float g_xr[LSEQ * 2 * DI];   // in_proj output (x | res)
__device__ float g_xp[LSEQ * DI];       // post conv+silu
__device__ float g_xdbl[LSEQ * XDBL];   // x_proj output fp32 (scan B/C need exactness)
__device__ float g_delta[LSEQ * DI];    // softplus(dt_proj)
__device__ float g_y[LSEQ * DI];        // scan output
__device__ float g_part[KSPL * PSTRIDE];// split-K partials for x_proj
__device__ float g_cp[SCH * NDN];       // scan chunk carry: product of dA
__device__ float g_ce[SCH * NDN];       // scan chunk carry: zero-start end state
__device__ float g_h0[SCH * NDN];       // scan chunk true start state
// half (packed half2) operands for fp16 GEMMs
__device__ unsigned g_xnh[LSEQ * DM / 2];       // rmsnorm output (GEMM A)
__device__ unsigned g_xdblh[LSEQ * XDBL / 2];   // xdbl half copy (dt_proj A)
__device__ unsigned g_yh[LSEQ * DI / 2];        // gated y (out_proj A)
__device__ unsigned g_embh[(size_t)VOC * DM / 2];   // embedding half (logits B)
__device__ unsigned g_wih[2 * 2 * DI * DM / 2]; // in_proj_w half
__device__ unsigned g_woh[2 * DM * DI / 2];     // out_proj_w half
__device__ unsigned g_wdth[2 * DI * DTR / 2];   // dt_proj_w half

__device__ __forceinline__ float siluf(float x) { return x / (1.0f + __expf(-x)); }
__device__ __forceinline__ float softplusf(float x) {
    return (x > 20.0f) ? x : log1pf(expf(x));
}
__device__ __forceinline__ unsigned pkh2(float x, float y) {
    __half2 h = __floats2half2_rn(x, y);
    return *(unsigned*)&h;
}
__device__ __forceinline__ void mma_f16(float c[4], const unsigned a[4], const unsigned b[2]) {
    asm volatile(
        "mma.sync.aligned.m16n8k16.row.col.f32.f16.f16.f32 "
        "{%0,%1,%2,%3}, {%4,%5,%6,%7}, {%8,%9}, {%0,%1,%2,%3};"
        : "+f"(c[0]), "+f"(c[1]), "+f"(c[2]), "+f"(c[3])
        : "r"(a[0]), "r"(a[1]), "r"(a[2]), "r"(a[3]), "r"(b[0]), "r"(b[1]));
}

// ---------------- fp32 -> packed half2 conversion ----------------
__global__ void cvt_half_kernel(const float* __restrict__ src, unsigned* __restrict__ dst) {
    int i = blockIdx.x * blockDim.x + threadIdx.x;
    float2 v = ((const float2*)src)[i];
    dst[i] = pkh2(v.x, v.y);
}

// ---------------- embedding gather ----------------
__global__ void embed_kernel(const int* __restrict__ ids, const float* __restrict__ emb) {
    int i = blockIdx.x * blockDim.x + threadIdx.x;
    int l = i >> 10, c = i & (DM - 1);
    g_x[i] = emb[(long)ids[l] * DM + c];
}

// ---------------- rmsnorm: one block per row; writes packed-half output ----------------
__global__ void rmsnorm_kernel(const float* __restrict__ x, const float* __restrict__ w) {
    int row = blockIdx.x;
    const float* xr = x + row * DM;
    float s = 0.0f;
    for (int c = threadIdx.x; c < DM; c += blockDim.x) { float v = xr[c]; s += v * v; }
    __shared__ float red[32];
    #pragma unroll
    for (int o = 16; o; o >>= 1) s += __shfl_xor_sync(~0u, s, o);
    if ((threadIdx.x & 31) == 0) red[threadIdx.x >> 5] = s;
    __syncthreads();
    if (threadIdx.x < 32) {
        float v = (threadIdx.x < (blockDim.x >> 5)) ? red[threadIdx.x] : 0.0f;
        #pragma unroll
        for (int o = 16; o; o >>= 1) v += __shfl_xor_sync(~0u, v, o);
        if (threadIdx.x == 0) red[0] = v;
    }
    __syncthreads();
    float inv = rsqrtf(red[0] / (float)DM + 1e-5f);
    for (int c2 = threadIdx.x; c2 < DM / 2; c2 += blockDim.x) {
        float a = xr[2 * c2]     * inv * w[2 * c2];
        float b = xr[2 * c2 + 1] * inv * w[2 * c2 + 1];
        g_xnh[row * (DM / 2) + c2] = pkh2(a, b);
    }
}

// ---------------- causal depthwise conv1d (k=4) + bias + silu ----------------
__global__ void conv_silu_kernel(const float* __restrict__ cw, const float* __restrict__ cb) {
    int i = blockIdx.x * blockDim.x + threadIdx.x;
    int l = i >> 11, d = i & (DI - 1);
    float acc = cb[d];
    #pragma unroll
    for (int t = 0; t < 4; t++) {
        int ls = l - 3 + t;
        if (ls >= 0) acc = fmaf(cw[d * 4 + t], g_xr[ls * (2 * DI) + d], acc);
    }
    g_xp[i] = siluf(acc);
}

// ---------------- scan pass A: per-chunk carries (P, E) ----------------
__global__ void scanA_kernel(const float* __restrict__ A_log) {
    int t = blockIdx.x * blockDim.x + threadIdx.x;
    int c = t / NDN;
    int q = t - c * NDN;
    int d = q >> 4, n = q & 15;
    float A_dn = -expf(A_log[d * DS + n]);
    float h = 0.0f, P = 1.0f;
    int l0 = c * CL;
    for (int i = 0; i < CL; i++) {
        int l = l0 + i;
        float dl = g_delta[l * DI + d];
        float u  = g_xp[l * DI + d];
        float Bv = g_xdbl[l * XDBL + DTR + n];
        float dA = __expf(dl * A_dn);
        h = fmaf(dA, h, dl * u * Bv);
        P *= dA;
    }
    g_cp[t] = P;
    g_ce[t] = h;
}

// ---------------- scan combine ----------------
__global__ void scanC_kernel() {
    int q = blockIdx.x * blockDim.x + threadIdx.x;
    float H = 0.0f;
    #pragma unroll
    for (int c = 0; c < SCH; c++) {
        g_h0[c * NDN + q] = H;
        H = fmaf(g_cp[c * NDN + q], H, g_ce[c * NDN + q]);
    }
}

// ---------------- scan pass B ----------------
__global__ void scanB_kernel(const float* __restrict__ A_log, const float* __restrict__ Dp) {
    int t = blockIdx.x * blockDim.x + threadIdx.x;
    int c = t / NDN;
    int q = t - c * NDN;
    int d = q >> 4, n = q & 15;
    float A_dn = -expf(A_log[d * DS + n]);
    float Dv = Dp[d];
    float h = g_h0[c * NDN + q];
    int l0 = c * CL;
    for (int i = 0; i < CL; i++) {
        int l = l0 + i;
        float dl = g_delta[l * DI + d];
        float u  = g_xp[l * DI + d];
        float Bv = g_xdbl[l * XDBL + DTR + n];
        float Cv = g_xdbl[l * XDBL + DTR + DS + n];
        float dA = __expf(dl * A_dn);
        h = fmaf(dA, h, dl * u * Bv);
        float py = h * Cv;
        #pragma unroll
        for (int o = 8; o; o >>= 1) py += __shfl_xor_sync(~0u, py, o);
        if (n == 0) g_y[l * DI + d] = py + u * Dv;
    }
}

// ---------------- gate: yh = half(y * silu(res))  (pairs) ----------------
__global__ void gate_kernel() {
    int i = blockIdx.x * blockDim.x + threadIdx.x;   // over LSEQ*DI/2
    int l = i / (DI / 2), dp = i - l * (DI / 2);
    int d = dp * 2;
    float r0 = g_xr[l * (2 * DI) + DI + d];
    float r1 = g_xr[l * (2 * DI) + DI + d + 1];
    float y0 = g_y[l * DI + d]     * siluf(r0);
    float y1 = g_y[l * DI + d + 1] * siluf(r1);
    g_yh[i] = pkh2(y0, y1);
}

// ================= FP16-native mma.sync m16n8k16 NT GEMM, 128x128, double-buffered =================
// A, B packed-half row-major (lda/ldb in HALF units). C fp32.
// EPI: 0 = none, 1 = +bias softplus, 2 = +residual.  SWAP: 1 -> blockIdx.x = row tile.
template <int EPI, int SWAP>
__global__ __launch_bounds__(256, 2)
void mma_h(const __half* __restrict__ A, int lda,
           const __half* __restrict__ B, int ldb,
           float* __restrict__ C, int ldc,
           int N, int K, const float* __restrict__ resid,
           const float* __restrict__ bias) {
    __shared__ unsigned sA[2][8][32][4];
    __shared__ unsigned sB[2][16][32][2];

    const int tid  = threadIdx.x;
    const int lane = tid & 31;
    const int warp = tid >> 5;
    const int wm = warp & 1;
    const int wn = warp >> 1;
    const int rowBase = (SWAP ? blockIdx.x : blockIdx.y) * 128;
    const int colBase = (SWAP ? blockIdx.y : blockIdx.x) * 128;

    // loader: thread handles row r = tid>>1, half-part hp = tid&1 (k = 8*hp .. 8*hp+7)
    const int r  = tid >> 1;
    const int hp = tid & 1;
    const __half* Arow = A + (long)(rowBase + r) * lda + hp * 8;
    const int nIdx = colBase + r;
    const __half* Brow = B + (long)nIdx * ldb + hp * 8;
    const bool bv = nIdx < N;

    float acc[4][4][4];
    #pragma unroll
    for (int i = 0; i < 4; i++)
        #pragma unroll
        for (int j = 0; j < 4; j++)
            #pragma unroll
            for (int q = 0; q < 4; q++) acc[i][j][q] = 0.0f;

    uint4 ra, rb;
    auto ldg = [&](int k0) {
        ra = *(const uint4*)(Arow + k0);
        rb = bv ? *(const uint4*)(Brow + k0) : make_uint4(0u, 0u, 0u, 0u);
    };
    // fragment scatter: pair kp = 4*hp + j -> lane low bits j, A reg = (rt>>3)+2*hp, B reg = hp
    auto sts = [&](int st) {
        const int mt = r >> 4, rt = r & 15;
        const int lr = (rt & 7) << 2;
        const int rA = (rt >> 3) + 2 * hp;
        sA[st][mt][lr | 0][rA] = ra.x;
        sA[st][mt][lr | 1][rA] = ra.y;
        sA[st][mt][lr | 2][rA] = ra.z;
        sA[st][mt][lr | 3][rA] = ra.w;
        const int nt = r >> 3, ct = r & 7;
        const int lb = ct << 2;
        sB[st][nt][lb | 0][hp] = rb.x;
        sB[st][nt][lb | 1][hp] = rb.y;
        sB[st][nt][lb | 2][hp] = rb.z;
        sB[st][nt][lb | 3][hp] = rb.w;
    };
    auto compute = [&](int st) {
        unsigned af[4][4];
        unsigned bf[4][2];
        #pragma unroll
        for (int i = 0; i < 4; i++) {
            uint4 v = *(const uint4*)&sA[st][wm * 4 + i][lane][0];
            af[i][0] = v.x; af[i][1] = v.y; af[i][2] = v.z; af[i][3] = v.w;
        }
        #pragma unroll
        for (int j = 0; j < 4; j++) {
            uint2 v = *(const uint2*)&sB[st][wn * 4 + j][lane][0];
            bf[j][0] = v.x; bf[j][1] = v.y;
        }
        #pragma unroll
        for (int i = 0; i < 4; i++)
            #pragma unroll
            for (int j = 0; j < 4; j++)
                mma_f16(acc[i][j], af[i], bf[j]);
    };

    ldg(0);
    sts(0);
    __syncthreads();
    int buf = 0;
    for (int k0 = 16; k0 < K; k0 += 16) {
        ldg(k0);
        compute(buf);
        sts(buf ^ 1);
        __syncthreads();
        buf ^= 1;
    }
    compute(buf);

    const int g   = lane >> 2;
    const int tig = lane & 3;
    #pragma unroll
    for (int i = 0; i < 4; i++) {
        const long row0 = rowBase + wm * 64 + i * 16 + g;
        #pragma unroll
        for (int j = 0; j < 4; j++) {
            const int col = colBase + wn * 32 + j * 8 + tig * 2;
            if (col < N) {
                float2 v01 = make_float2(acc[i][j][0], acc[i][j][1]);
                float2 v23 = make_float2(acc[i][j][2], acc[i][j][3]);
                if (EPI == 1) {
                    float b0 = bias[col], b1 = bias[col + 1];
                    v01.x = softplusf(v01.x + b0); v01.y = softplusf(v01.y + b1);
                    v23.x = softplusf(v23.x + b0); v23.y = softplusf(v23.y + b1);
                }
                if (EPI == 2) {
                    float2 t0 = *(const float2*)&resid[row0 * ldc + col];
                    float2 t1 = *(const float2*)&resid[(row0 + 8) * ldc + col];
                    v01.x += t0.x; v01.y += t0.y;
                    v23.x += t1.x; v23.y += t1.y;
                }
                *(float2*)&C[row0 * ldc + col]       = v01;
                *(float2*)&C[(row0 + 8) * ldc + col] = v23;
            }
        }
    }
}

// ---------------- fp32 NT SGEMM (split-K partials for x_proj; exact path) ----------------
__global__ __launch_bounds__(256, 2)
void sgemm_splitk(const float* __restrict__ A, int lda,
                  const float* __restrict__ B, int ldb,
                  float* __restrict__ C, int ldc,
                  int N, int K) {
    __shared__ float As[8][128];
    __shared__ float Bs[8][128];
    const int tid = threadIdx.x;
    const int rowBase = blockIdx.y * 128;
    const int colBase = blockIdx.x * 128;
    const int kOff = blockIdx.z * K;
    C += (size_t)blockIdx.z * PSTRIDE;

    const int aRow = tid >> 1;
    const int aCol = (tid & 1) << 2;
    const float* Aptr = A + (long)(rowBase + aRow) * lda + aCol + kOff;
    const bool bValid = (colBase + aRow) < N;
    const float* Bptr = B + (long)(colBase + aRow) * ldb + aCol + kOff;

    const int tr = (tid >> 4) << 3;
    const int tc = (tid & 15) << 3;

    float acc[8][8];
    #pragma unroll
    for (int i = 0; i < 8; i++)
        #pragma unroll
        for (int j = 0; j < 8; j++) acc[i][j] = 0.0f;

    for (int k0 = 0; k0 < K; k0 += 8) {
        float4 va = *(const float4*)(Aptr + k0);
        float4 vb = bValid ? *(const float4*)(Bptr + k0) : make_float4(0.f, 0.f, 0.f, 0.f);
        As[aCol + 0][aRow] = va.x; As[aCol + 1][aRow] = va.y;
        As[aCol + 2][aRow] = va.z; As[aCol + 3][aRow] = va.w;
        Bs[aCol + 0][aRow] = vb.x; Bs[aCol + 1][aRow] = vb.y;
        Bs[aCol + 2][aRow] = vb.z; Bs[aCol + 3][aRow] = vb.w;
        __syncthreads();
        #pragma unroll
        for (int kk = 0; kk < 8; kk++) {
            float rm[8], rn[8];
            *(float4*)(rm)     = *(const float4*)&As[kk][tr];
            *(float4*)(rm + 4) = *(const float4*)&As[kk][tr + 4];
            *(float4*)(rn)     = *(const float4*)&Bs[kk][tc];
            *(float4*)(rn + 4) = *(const float4*)&Bs[kk][tc + 4];
            #pragma unroll
            for (int i = 0; i < 8; i++)
                #pragma unroll
                for (int j = 0; j < 8; j++)
                    acc[i][j] = fmaf(rm[i], rn[j], acc[i][j]);
        }
        __syncthreads();
    }

    #pragma unroll
    for (int i = 0; i < 8; i++) {
        const long rr = rowBase + tr + i;
        #pragma unroll
        for (int j = 0; j < 8; j++) {
            const int c = colBase + tc + j;
            if (c < N) C[rr * ldc + c] = acc[i][j];
        }
    }
}

// ---------------- split-K reduction for x_proj (writes fp32 + half copy) ----------------
__global__ void splitk_reduce_kernel() {
    int i = blockIdx.x * blockDim.x + threadIdx.x;   // over PSTRIDE/2 (pairs)
    int i0 = 2 * i, i1 = 2 * i + 1;
    float s0 = 0.0f, s1 = 0.0f;
    #pragma unroll
    for (int p = 0; p < KSPL; p++) {
        s0 += g_part[p * PSTRIDE + i0];
        s1 += g_part[p * PSTRIDE + i1];
    }
    g_xdbl[i0] = s0;
    g_xdbl[i1] = s1;
    g_xdblh[i] = pkh2(s0, s1);
}

// ---------------- host orchestration ----------------
extern "C" void kernel_launch(void* const* d_in, const int* in_sizes, int n_in,
                              void* d_out, int out_size) {
    const int*   ids        = (const int*)  d_in[0];
    const float* emb        = (const float*)d_in[1];
    const float* in_proj_w  = (const float*)d_in[2];
    const float* conv_w     = (const float*)d_in[3];
    const float* conv_b     = (const float*)d_in[4];
    const float* x_proj_w   = (const float*)d_in[5];
    const float* dt_proj_w  = (const float*)d_in[6];
    const float* dt_proj_b  = (const float*)d_in[7];
    const float* A_log      = (const float*)d_in[8];
    const float* D_param    = (const float*)d_in[9];
    const float* out_proj_w = (const float*)d_in[10];
    const float* norm_w     = (const float*)d_in[11];
    const float* norm_f_w   = (const float*)d_in[12];
    float* out = (float*)d_out;

    float *x, *xr, *xp, *part;
    unsigned *xnh, *xdblh, *yh, *embh, *wih, *woh, *wdth;
    cudaGetSymbolAddress((void**)&x,     g_x);
    cudaGetSymbolAddress((void**)&xr,    g_xr);
    cudaGetSymbolAddress((void**)&xp,    g_xp);
    cudaGetSymbolAddress((void**)&part,  g_part);
    cudaGetSymbolAddress((void**)&xnh,   g_xnh);
    cudaGetSymbolAddress((void**)&xdblh, g_xdblh);
    cudaGetSymbolAddress((void**)&yh,    g_yh);
    cudaGetSymbolAddress((void**)&embh,  g_embh);
    cudaGetSymbolAddress((void**)&wih,   g_wih);
    cudaGetSymbolAddress((void**)&woh,   g_woh);
    cudaGetSymbolAddress((void**)&wdth,  g_wdth);
    float *y_f, *delta_f;
    cudaGetSymbolAddress((void**)&y_f,     g_y);
    cudaGetSymbolAddress((void**)&delta_f, g_delta);

    // once-per-launch weight conversions (fp32 -> packed half2)
    cvt_half_kernel<<<((size_t)VOC * DM / 2) / 256, 256>>>(emb, embh);
    cvt_half_kernel<<<(2 * 2 * DI * DM / 2) / 256, 256>>>(in_proj_w, wih);
    cvt_half_kernel<<<(2 * DM * DI / 2) / 256, 256>>>(out_proj_w, woh);
    cvt_half_kernel<<<(2 * DI * DTR / 2) / 256, 256>>>(dt_proj_w, wdth);

    embed_kernel<<<(LSEQ * DM) / 256, 256>>>(ids, emb);

    for (int layer = 0; layer < 2; layer++) {
        rmsnorm_kernel<<<LSEQ, 256>>>(x, norm_w + layer * DM);   // -> g_xnh

        // x_and_res = xn @ in_proj_w^T : [2048, 4096]   (fp16-native)
        mma_h<0, 0><<<dim3((2 * DI) / 128, LSEQ / 128), 256>>>(
            (const __half*)xnh, DM,
            (const __half*)(wih) + (size_t)layer * 2 * DI * DM, DM,
            xr, 2 * DI, 2 * DI, DM, (const float*)0, (const float*)0);

        conv_silu_kernel<<<(LSEQ * DI) / 256, 256>>>(
            conv_w + (size_t)layer * DI * 4, conv_b + (size_t)layer * DI);

        // x_dbl = xp @ x_proj_w^T : [2048, 96]  (fp32 split-K exact)
        sgemm_splitk<<<dim3(1, LSEQ / 128, KSPL), 256>>>(
            xp, DI, x_proj_w + (size_t)layer * XDBL * DI, DI,
            part, XDBL, XDBL, DI / KSPL);
        splitk_reduce_kernel<<<(PSTRIDE / 2) / 256, 256>>>();

        // delta = softplus(x_dbl[:, :64] @ dt_proj_w^T + b)   (fp16-native, K=64)
        mma_h<1, 0><<<dim3(DI / 128, LSEQ / 128), 256>>>(
            (const __half*)xdblh, XDBL,
            (const __half*)(wdth) + (size_t)layer * DI * DTR, DTR,
            delta_f, DI, DI, DTR, (const float*)0, dt_proj_b + (size_t)layer * DI);

        // chunked two-pass scan
        scanA_kernel<<<(SCH * NDN) / 256, 256>>>(A_log + (size_t)layer * DI * DS);
        scanC_kernel<<<NDN / 256, 256>>>();
        scanB_kernel<<<(SCH * NDN) / 256, 256>>>(
            A_log + (size_t)layer * DI * DS, D_param + (size_t)layer * DI);
        gate_kernel<<<(LSEQ * DI / 2) / 256, 256>>>();          // -> g_yh

        // x = x + ygated @ out_proj_w^T : [2048, 1024]   (fp16-native)
        mma_h<2, 0><<<dim3(DM / 128, LSEQ / 128), 256>>>(
            (const __half*)yh, DI,
            (const __half*)(woh) + (size_t)layer * DM * DI, DI,
            x, DM, DM, DI, x, (const float*)0);
    }

    rmsnorm_kernel<<<LSEQ, 256>>>(x, norm_f_w);                  // -> g_xnh

    // logits = xf @ embedding^T : [2048, 50264]  (fp16-native; row tiles fastest)
    mma_h<0, 1><<<dim3(LSEQ / 128, (VOC + 127) / 128), 256>>>(
        (const __half*)xnh, DM, (const __half*)embh, DM,
        out, VOC, VOC, DM, (const float*)0, (const float*)0);
}